// round 16
// baseline (speedup 1.0000x reference)
#include <cuda_runtime.h>
#include <cuda_fp16.h>

#define N_USER    50000
#define N_ITEM    10000
#define NUM_NODES 60000
#define EMB_D     64
#define N_EDGES   2000000
#define N_GROUPS8 (N_EDGES / 8)   // 8 edges per 8-lane group

// Table scale: keeps fp16 products in normal range.
#define TBL_SCALE      512.0f
#define INV_TBL_SCALE2 (1.0f / (512.0f * 512.0f))   // 2^-18

// Fused, pre-scaled node table in fp16: row = 64 half = 128 B (one L1 line).
__device__ __half g_nodes[NUM_NODES * EMB_D];

// Phase 1: 8 threads per node; each thread fuses 2 consecutive float4 chunks
// (8 dims) of ONE node. Indices loaded once per thread; 2x table loads in
// flight vs the 16-thread version; single STG.128 epilogue.
__global__ __launch_bounds__(256) void build_nodes_kernel(
        const float* __restrict__ user_emb,
        const float* __restrict__ item_emb,
        const float* __restrict__ tag_emb,
        const float* __restrict__ testid_emb,
        const float* __restrict__ bigcat_emb,
        const float* __restrict__ daydiff_emb,
        const int*  __restrict__ item_tags,
        const int*  __restrict__ item_testids,
        const int*  __restrict__ item_bigcat,
        const int*  __restrict__ user_daydiff) {
    unsigned int t = blockIdx.x * blockDim.x + threadIdx.x;
    unsigned int node = t >> 3;
    unsigned int sub  = t & 7u;          // 8 chunks of 8 floats
    if (node >= NUM_NODES) return;
    unsigned int off = sub * 8u;         // float offset of first chunk

    const float alpha = 1.0f / 3.0f;
    float4 r0, r1;
    if (node < N_USER) {
        const float s = 0.5f * alpha * TBL_SCALE;
        int dd = user_daydiff[node];
        const float* up = user_emb    + (size_t)node * EMB_D + off;
        const float* dp = daydiff_emb + (size_t)dd   * EMB_D + off;
        float4 u0 = *(const float4*)(up);
        float4 u1 = *(const float4*)(up + 4);
        float4 d0 = *(const float4*)(dp);
        float4 d1 = *(const float4*)(dp + 4);
        r0.x = (u0.x + d0.x) * s; r0.y = (u0.y + d0.y) * s;
        r0.z = (u0.z + d0.z) * s; r0.w = (u0.w + d0.w) * s;
        r1.x = (u1.x + d1.x) * s; r1.y = (u1.y + d1.y) * s;
        r1.z = (u1.z + d1.z) * s; r1.w = (u1.w + d1.w) * s;
    } else {
        const float s = 0.25f * alpha * TBL_SCALE;
        unsigned int it = node - N_USER;
        int tg = item_tags[it];
        int ts = item_testids[it];
        int bc = item_bigcat[it];
        const float* ap = item_emb   + (size_t)it * EMB_D + off;
        const float* bp = tag_emb    + (size_t)tg * EMB_D + off;
        const float* cp = testid_emb + (size_t)ts * EMB_D + off;
        const float* ep = bigcat_emb + (size_t)bc * EMB_D + off;
        float4 a0 = *(const float4*)(ap);
        float4 a1 = *(const float4*)(ap + 4);
        float4 b0 = *(const float4*)(bp);
        float4 b1 = *(const float4*)(bp + 4);
        float4 c0 = *(const float4*)(cp);
        float4 c1 = *(const float4*)(cp + 4);
        float4 e0 = *(const float4*)(ep);
        float4 e1 = *(const float4*)(ep + 4);
        r0.x = (a0.x + b0.x + c0.x + e0.x) * s;
        r0.y = (a0.y + b0.y + c0.y + e0.y) * s;
        r0.z = (a0.z + b0.z + c0.z + e0.z) * s;
        r0.w = (a0.w + b0.w + c0.w + e0.w) * s;
        r1.x = (a1.x + b1.x + c1.x + e1.x) * s;
        r1.y = (a1.y + b1.y + c1.y + e1.y) * s;
        r1.z = (a1.z + b1.z + c1.z + e1.z) * s;
        r1.w = (a1.w + b1.w + c1.w + e1.w) * s;
    }
    __half2 h0 = __floats2half2_rn(r0.x, r0.y);
    __half2 h1 = __floats2half2_rn(r0.z, r0.w);
    __half2 h2 = __floats2half2_rn(r1.x, r1.y);
    __half2 h3 = __floats2half2_rn(r1.z, r1.w);
    uint4 packed;
    packed.x = *(const unsigned int*)&h0;
    packed.y = *(const unsigned int*)&h1;
    packed.z = *(const unsigned int*)&h2;
    packed.w = *(const unsigned int*)&h3;
    *(uint4*)((char*)g_nodes + (size_t)node * 128u + sub * 16u) = packed;
}

// half2 partial dot of 16 halves (one uint4 pair): 4 HMUL2 + 3 HADD2.
__device__ __forceinline__ __half2 pdot(uint4 a, uint4 b) {
    const __half2* pa = (const __half2*)&a;
    const __half2* pb = (const __half2*)&b;
    __half2 m0 = __hmul2(pa[0], pb[0]);
    __half2 m1 = __hmul2(pa[1], pb[1]);
    __half2 m2 = __hmul2(pa[2], pb[2]);
    __half2 m3 = __hmul2(pa[3], pb[3]);
    return __hadd2(__hadd2(m0, m1), __hadd2(m2, m3));
}

__device__ __forceinline__ __half2 shfl_h2(__half2 v, int ofs) {
    unsigned int u = *(unsigned int*)&v;
    u = __shfl_xor_sync(0xffffffffu, u, ofs);
    return *(__half2*)&u;
}

// Phase 2: 8 edges per 8-lane group — byte-exact R5 structure (proven best:
// 16 flat LDG.128 gathers, ~40 regs, 6 blocks/SM). 7-SHFL value-halving
// reduction; lane `sub` ends owning edge g*8+sub -> warp-coalesced store.
__global__ __launch_bounds__(256) void edge_dot_kernel(
        const int4* __restrict__ src4,
        const int4* __restrict__ dst4,
        float* __restrict__ out) {
    unsigned int t = blockIdx.x * blockDim.x + threadIdx.x;
    unsigned int g   = t >> 3;
    unsigned int sub = t & 7u;
    if (g >= N_GROUPS8) return;

    int4 sL = src4[g * 2u];
    int4 sH = src4[g * 2u + 1u];
    int4 dL = dst4[g * 2u];
    int4 dH = dst4[g * 2u + 1u];

    const uint4* np = (const uint4*)g_nodes + sub;   // row = 8 uint4

    uint4 a0 = np[(unsigned)sL.x * 8u];
    uint4 b0 = np[(unsigned)dL.x * 8u];
    uint4 a1 = np[(unsigned)sL.y * 8u];
    uint4 b1 = np[(unsigned)dL.y * 8u];
    uint4 a2 = np[(unsigned)sL.z * 8u];
    uint4 b2 = np[(unsigned)dL.z * 8u];
    uint4 a3 = np[(unsigned)sL.w * 8u];
    uint4 b3 = np[(unsigned)dL.w * 8u];
    uint4 a4 = np[(unsigned)sH.x * 8u];
    uint4 b4 = np[(unsigned)dH.x * 8u];
    uint4 a5 = np[(unsigned)sH.y * 8u];
    uint4 b5 = np[(unsigned)dH.y * 8u];
    uint4 a6 = np[(unsigned)sH.z * 8u];
    uint4 b6 = np[(unsigned)dH.z * 8u];
    uint4 a7 = np[(unsigned)sH.w * 8u];
    uint4 b7 = np[(unsigned)dH.w * 8u];

    __half2 p0 = pdot(a0, b0);
    __half2 p1 = pdot(a1, b1);
    __half2 p2 = pdot(a2, b2);
    __half2 p3 = pdot(a3, b3);
    __half2 p4 = pdot(a4, b4);
    __half2 p5 = pdot(a5, b5);
    __half2 p6 = pdot(a6, b6);
    __half2 p7 = pdot(a7, b7);

    bool bit2 = (sub & 4u) != 0u;
    bool bit1 = (sub & 2u) != 0u;
    bool bit0 = (sub & 1u) != 0u;

    // Stage 1 (xor 4): 8 -> 4 values.
    __half2 w0, w1, w2, w3;
    {
        __half2 q0 = bit2 ? p0 : p4;
        __half2 q1 = bit2 ? p1 : p5;
        __half2 q2 = bit2 ? p2 : p6;
        __half2 q3 = bit2 ? p3 : p7;
        w0 = __hadd2(bit2 ? p4 : p0, shfl_h2(q0, 4));
        w1 = __hadd2(bit2 ? p5 : p1, shfl_h2(q1, 4));
        w2 = __hadd2(bit2 ? p6 : p2, shfl_h2(q2, 4));
        w3 = __hadd2(bit2 ? p7 : p3, shfl_h2(q3, 4));
    }
    // Stage 2 (xor 2): 4 -> 2.
    __half2 x0, x1;
    {
        __half2 q0 = bit1 ? w0 : w2;
        __half2 q1 = bit1 ? w1 : w3;
        x0 = __hadd2(bit1 ? w2 : w0, shfl_h2(q0, 2));
        x1 = __hadd2(bit1 ? w3 : w1, shfl_h2(q1, 2));
    }
    // Stage 3 (xor 1): 2 -> 1. Lane `sub` owns edge g*8+sub.
    __half2 q = bit0 ? x0 : x1;
    __half2 y = __hadd2(bit0 ? x1 : x0, shfl_h2(q, 1));

    float2 f = __half22float2(y);
    out[g * 8u + sub] = (f.x + f.y) * INV_TBL_SCALE2;
}

extern "C" void kernel_launch(void* const* d_in, const int* in_sizes, int n_in,
                              void* d_out, int out_size) {
    const float* user_emb     = (const float*)d_in[0];
    const float* item_emb     = (const float*)d_in[1];
    const float* tag_emb      = (const float*)d_in[2];
    const float* testid_emb   = (const float*)d_in[3];
    const float* bigcat_emb   = (const float*)d_in[4];
    const float* daydiff_emb  = (const float*)d_in[5];
    const int*   edge_index   = (const int*)d_in[6];   // [2, N_EDGES] int32
    const int*   item_tags    = (const int*)d_in[7];
    const int*   item_testids = (const int*)d_in[8];
    const int*   item_bigcat  = (const int*)d_in[9];
    const int*   user_daydiff = (const int*)d_in[10];

    // Phase 1: 60000 nodes * 8 threads
    {
        unsigned int total = NUM_NODES * 8u;
        unsigned int threads = 256;
        unsigned int blocks = (total + threads - 1) / threads;
        build_nodes_kernel<<<blocks, threads>>>(user_emb, item_emb, tag_emb,
                                                testid_emb, bigcat_emb, daydiff_emb,
                                                item_tags, item_testids, item_bigcat,
                                                user_daydiff);
    }

    // Phase 2: 250K groups * 8 threads = 2M threads (R5 launch shape)
    {
        const int4* src4 = (const int4*)edge_index;
        const int4* dst4 = (const int4*)(edge_index + N_EDGES);
        unsigned int total = N_GROUPS8 * 8u;
        unsigned int threads = 256;
        unsigned int blocks = (total + threads - 1) / threads;
        edge_dot_kernel<<<blocks, threads>>>(src4, dst4, (float*)d_out);
    }
}